// round 8
// baseline (speedup 1.0000x reference)
#include <cuda_runtime.h>
#include <cuda_bf16.h>
#include <math.h>

// Problem shape (fixed by dataset): X [2048,16,32,32] f32, weight [32,32] f32.
#define NM      32768          // 2048*16 matrices
#define NEL     1024           // 32*32
#define LM_WPB  8              // warps (matrices) per block in heavy kernels
#define LM_BLOCKS (NM / LM_WPB)  // 4096

// ---------------- device scratch (static, no allocation) ----------------
__device__ float d_partA[256 * NEL];        // stage-A block partials
__device__ float d_g0[NEL];                 // arithmetic mean of X
__device__ float d_gs[NEL];                 // sqrtm(g0)
__device__ float d_gis[NEL];                // invsqrtm(g0)
__device__ float d_ws[NEL];                 // sqrtm(weight)
__device__ float d_partT[LM_BLOCKS * NEL];  // per-block logm partial sums (16 MB)
__device__ float d_partT2[64 * NEL];        // second-level partials
__device__ float d_t[NEL];                  // mean of logms
__device__ float d_Af[NEL];                 // final congruence factor ws*gis2

// ---------------- small helpers ----------------
__device__ __forceinline__ void get_pq(int r, int k, int& p, int& q) {
    if (k == 0) { p = 31; q = r; }
    else {
        p = r + k; if (p >= 31) p -= 31;
        q = r - k; if (q < 0)  q += 31;
    }
}

// Warp-cooperative cyclic Jacobi eigensolver for a 32x32 symmetric matrix.
// sA: 32x32 matrix, row-major padded stride 33 (1056 floats). On exit the
// diagonal holds eigenvalues. sV (same layout) holds eigenvectors in columns:
// A_in = V diag(lambda) V^T.  sCS: >= 32 floats scratch.
__device__ void warp_eigh32(float* sA, float* sV, float* sCS, int lane) {
    #pragma unroll
    for (int i = 0; i < 32; i++) sV[i * 33 + lane] = (i == lane) ? 1.0f : 0.0f;
    __syncwarp();

    #pragma unroll 1
    for (int sweep = 0; sweep < 10; sweep++) {
        float off = 0.0f;
        #pragma unroll 1
        for (int r = 0; r < 31; r++) {
            // phase 1: 16 lanes compute the 16 disjoint rotations of this round
            if (lane < 16) {
                int p, q; get_pq(r, lane, p, q);
                float app = sA[p * 33 + p];
                float aqq = sA[q * 33 + q];
                float apq = sA[p * 33 + q];
                off += apq * apq;
                float c = 1.0f, s = 0.0f;
                if (fabsf(apq) > 1e-9f * (fabsf(app) + fabsf(aqq) + 1e-30f)) {
                    float theta = 0.5f * (aqq - app) / apq;
                    float tt = 1.0f / (fabsf(theta) + sqrtf(1.0f + theta * theta));
                    tt = copysignf(tt, theta);
                    c = rsqrtf(1.0f + tt * tt);
                    s = tt * c;
                }
                sCS[lane]      = c;
                sCS[16 + lane] = s;
            }
            __syncwarp();
            // phase 2: column rotations of A and V (lane = row index; conflict-free)
            #pragma unroll
            for (int k = 0; k < 16; k++) {
                float s = sCS[16 + k];
                if (s != 0.0f) {                 // warp-uniform branch
                    float c = sCS[k];
                    int p, q; get_pq(r, k, p, q);
                    float x = sA[lane * 33 + p], y = sA[lane * 33 + q];
                    sA[lane * 33 + p] = c * x - s * y;
                    sA[lane * 33 + q] = s * x + c * y;
                    float vx = sV[lane * 33 + p], vy = sV[lane * 33 + q];
                    sV[lane * 33 + p] = c * vx - s * vy;
                    sV[lane * 33 + q] = s * vx + c * vy;
                }
            }
            __syncwarp();
            // phase 3: row rotations of A (lane = column index; conflict-free)
            #pragma unroll
            for (int k = 0; k < 16; k++) {
                float s = sCS[16 + k];
                if (s != 0.0f) {
                    float c = sCS[k];
                    int p, q; get_pq(r, k, p, q);
                    float x = sA[p * 33 + lane], y = sA[q * 33 + lane];
                    sA[p * 33 + lane] = c * x - s * y;
                    sA[q * 33 + lane] = s * x + c * y;
                }
            }
            __syncwarp();
        }
        // convergence: off-diagonal Frobenius^2 vs diagonal Frobenius^2
        float dd  = sA[lane * 33 + lane];
        float dsq = dd * dd;
        #pragma unroll
        for (int o = 16; o > 0; o >>= 1) {
            off += __shfl_xor_sync(0xffffffffu, off, o);
            dsq += __shfl_xor_sync(0xffffffffu, dsq, o);
        }
        if (off <= 1e-10f * dsq) break;
    }
    __syncwarp();
}

struct FnLog   { __device__ float operator()(float x) const { return logf(fmaxf(x, 1e-30f)); } };
struct FnExp   { __device__ float operator()(float x) const { return expf(x); } };
struct FnSqrt  { __device__ float operator()(float x) const { return sqrtf(fmaxf(x, 0.0f)); } };
struct FnRsqrt { __device__ float operator()(float x) const { return rsqrtf(fmaxf(x, 1e-30f)); } };

// out[i][j] = sum_k V[i][k] f(lambda_k) V[j][k].
// out may alias sA (diag is read before any write); out must NOT alias sV.
template <class F>
__device__ void warp_matfn(const float* sA, const float* sV, float* sTmp,
                           float* out, int ostride, int lane, F f) {
    sTmp[lane] = f(sA[lane * 33 + lane]);
    __syncwarp();
    float vj[32];
    #pragma unroll
    for (int k = 0; k < 32; k++) vj[k] = sV[lane * 33 + k];
    float acc[32];
    #pragma unroll
    for (int i = 0; i < 32; i++) acc[i] = 0.0f;
    #pragma unroll
    for (int k = 0; k < 32; k++) {
        float coef = sTmp[k] * vj[k];
        #pragma unroll
        for (int i = 0; i < 32; i++) acc[i] += sV[i * 33 + k] * coef;
    }
    __syncwarp();
    #pragma unroll
    for (int i = 0; i < 32; i++) out[i * ostride + lane] = acc[i];
    __syncwarp();
}

// C = A * B (all 32x32, pad-33 smem). C must not alias A or B.
__device__ void warp_mm(float* C, const float* A, const float* B, int lane) {
    float bcol[32];
    #pragma unroll
    for (int l = 0; l < 32; l++) bcol[l] = B[l * 33 + lane];
    #pragma unroll
    for (int i = 0; i < 32; i++) {
        float acc = 0.0f;
        #pragma unroll
        for (int l = 0; l < 32; l++) acc += A[i * 33 + l] * bcol[l];
        C[i * 33 + lane] = acc;
    }
    __syncwarp();
}

// ---------------- stage A: arithmetic mean of all matrices ----------------
__global__ void k_sumA(const float* __restrict__ X) {
    int b = blockIdx.x, t = threadIdx.x;
    const int MPB = NM / 256;   // 128 matrices per block
    const float* base = X + (size_t)b * MPB * NEL;
    float a0 = 0.f, a1 = 0.f, a2 = 0.f, a3 = 0.f;
    for (int m = 0; m < MPB; m++) {
        const float* p = base + (size_t)m * NEL;
        a0 += p[t];        a1 += p[t + 256];
        a2 += p[t + 512];  a3 += p[t + 768];
    }
    d_partA[b * NEL + t]       = a0;
    d_partA[b * NEL + t + 256] = a1;
    d_partA[b * NEL + t + 512] = a2;
    d_partA[b * NEL + t + 768] = a3;
}

__global__ void k_redA() {
    int e = threadIdx.x;
    float s = 0.f;
    for (int b = 0; b < 256; b++) s += d_partA[b * NEL + e];
    d_g0[e] = s * (1.0f / (float)NM);
}

// ---------------- stage B: gs/gis from g0; ws from weight ----------------
__global__ void k_prep(const float* __restrict__ W) {
    __shared__ float sm[2 * 2160];
    int w = threadIdx.x >> 5, lane = threadIdx.x & 31;
    float* sA  = sm + w * 2160;
    float* sV  = sA + 1056;
    float* sCS = sV + 1056;
    const float* src = (w == 0) ? d_g0 : W;
    #pragma unroll
    for (int i = 0; i < 32; i++) sA[i * 33 + lane] = src[i * 32 + lane];
    __syncwarp();
    warp_eigh32(sA, sV, sCS, lane);
    if (w == 0) {
        warp_matfn(sA, sV, sCS, d_gs,  32, lane, FnSqrt());
        warp_matfn(sA, sV, sCS, d_gis, 32, lane, FnRsqrt());
    } else {
        warp_matfn(sA, sV, sCS, d_ws,  32, lane, FnSqrt());
    }
}

// ---------------- stage C: per-matrix logm(sym(gis X gis)), block-summed --
__global__ __launch_bounds__(256) void k_logmean(const float* __restrict__ X) {
    extern __shared__ float sm[];
    float* gis_s = sm;                                  // 1056
    int tid = threadIdx.x, w = tid >> 5, lane = tid & 31;
    for (int e = tid; e < NEL; e += 256)
        gis_s[(e >> 5) * 33 + (e & 31)] = d_gis[e];
    __syncthreads();

    float* sA  = sm + 1056 + w * 2160;
    float* sV  = sA + 1056;
    float* sCS = sV + 1056;                             // 48 floats

    size_t m = (size_t)blockIdx.x * LM_WPB + w;
    const float* xp = X + m * NEL;
    #pragma unroll
    for (int i = 0; i < 32; i++) sA[i * 33 + lane] = xp[i * 32 + lane];
    __syncwarp();

    // U = X * gis  (column `lane` in registers)
    float gcol[32];
    #pragma unroll
    for (int l = 0; l < 32; l++) gcol[l] = gis_s[l * 33 + lane];
    float u[32];
    #pragma unroll
    for (int i = 0; i < 32; i++) {
        float a = 0.f;
        #pragma unroll
        for (int l = 0; l < 32; l++) a += sA[i * 33 + l] * gcol[l];
        u[i] = a;
    }
    __syncwarp();
    // M = gis * U, overwrite sA
    #pragma unroll
    for (int i = 0; i < 32; i++) {
        float a = 0.f;
        #pragma unroll
        for (int l = 0; l < 32; l++) a += gis_s[i * 33 + l] * u[l];
        sA[i * 33 + lane] = a;
    }
    __syncwarp();
    // symmetrize (matches reference _sym)
    for (int i = 0; i < lane; i++) {
        float a = sA[i * 33 + lane], b = sA[lane * 33 + i];
        float h = 0.5f * (a + b);
        sA[i * 33 + lane] = h; sA[lane * 33 + i] = h;
    }
    __syncwarp();

    warp_eigh32(sA, sV, sCS, lane);
    warp_matfn(sA, sV, sCS, sA, 33, lane, FnLog());   // sA = logm(M)

    __syncthreads();
    // deterministic fixed-order block reduction over the 8 warp buffers
    float* outp = d_partT + (size_t)blockIdx.x * NEL;
    for (int e = tid; e < NEL; e += 256) {
        int i = e >> 5, j = e & 31;
        float s = 0.f;
        #pragma unroll
        for (int ww = 0; ww < LM_WPB; ww++)
            s += sm[1056 + ww * 2160 + i * 33 + j];
        outp[e] = s;
    }
}

__global__ void k_redT1() {
    int b = blockIdx.x, e = threadIdx.x;
    float s = 0.f;
    for (int i = 0; i < LM_BLOCKS / 64; i++)
        s += d_partT[((size_t)(b * (LM_BLOCKS / 64) + i)) * NEL + e];
    d_partT2[b * NEL + e] = s;
}

__global__ void k_redT2() {
    int e = threadIdx.x;
    float s = 0.f;
    for (int b = 0; b < 64; b++) s += d_partT2[b * NEL + e];
    d_t[e] = s * (1.0f / (float)NM);
}

// ---------------- stage D: Karcher update + final factor A_f --------------
__global__ void k_final() {
    __shared__ float sm[4 * 1056 + 48];
    float* sA  = sm;
    float* sV  = sm + 1056;
    float* sB  = sm + 2112;
    float* sC  = sm + 3168;
    float* sCS = sm + 4224;
    int lane = threadIdx.x;

    // E = expm(t)
    #pragma unroll
    for (int i = 0; i < 32; i++) sA[i * 33 + lane] = d_t[i * 32 + lane];
    __syncwarp();
    warp_eigh32(sA, sV, sCS, lane);
    warp_matfn(sA, sV, sCS, sB, 33, lane, FnExp());   // sB = E

    // g = sym(gs * E * gs)
    #pragma unroll
    for (int i = 0; i < 32; i++) sC[i * 33 + lane] = d_gs[i * 32 + lane];
    __syncwarp();
    warp_mm(sA, sC, sB, lane);                        // sA = gs*E
    warp_mm(sV, sA, sC, lane);                        // sV = gs*E*gs
    for (int i = 0; i < lane; i++) {
        float a = sV[i * 33 + lane], b = sV[lane * 33 + i];
        float h = 0.5f * (a + b);
        sV[i * 33 + lane] = h; sV[lane * 33 + i] = h;
    }
    __syncwarp();

    // gis2 = invsqrtm(g)
    warp_eigh32(sV, sB, sCS, lane);                   // matrix in sV, vectors in sB
    warp_matfn(sV, sB, sCS, sA, 33, lane, FnRsqrt()); // sA = gis2

    // A_f = ws * gis2
    #pragma unroll
    for (int i = 0; i < 32; i++) sC[i * 33 + lane] = d_ws[i * 32 + lane];
    __syncwarp();
    warp_mm(sB, sC, sA, lane);                        // sB = ws*gis2
    #pragma unroll
    for (int i = 0; i < 32; i++) d_Af[i * 32 + lane] = sB[i * 33 + lane];
}

// ---------------- stage E: out = A_f * X * A_f^T per matrix ---------------
__global__ __launch_bounds__(256) void k_apply(const float* __restrict__ X,
                                               float* __restrict__ out) {
    extern __shared__ float sm[];
    float* A_s = sm;                                   // 1056, block-shared
    int tid = threadIdx.x, w = tid >> 5, lane = tid & 31;
    for (int e = tid; e < NEL; e += 256)
        A_s[(e >> 5) * 33 + (e & 31)] = d_Af[e];
    __syncthreads();

    float* sX = sm + 1056 + w * 1056;                  // per-warp T buffer
    size_t m = (size_t)blockIdx.x * LM_WPB + w;
    const float* xp = X + m * NEL;

    float xcol[32];
    #pragma unroll
    for (int i = 0; i < 32; i++) xcol[i] = xp[i * 32 + lane];  // X[:,lane]

    // T = A * X  (column `lane` in registers)
    float t[32];
    #pragma unroll
    for (int i = 0; i < 32; i++) {
        float a = 0.f;
        #pragma unroll
        for (int l = 0; l < 32; l++) a += A_s[i * 33 + l] * xcol[l];
        t[i] = a;
    }
    #pragma unroll
    for (int i = 0; i < 32; i++) sX[i * 33 + lane] = t[i];
    __syncwarp();

    // Y = T * A^T :  Y[i][lane] = sum_l T[i][l] * A[lane][l]
    float arow[32];
    #pragma unroll
    for (int l = 0; l < 32; l++) arow[l] = A_s[lane * 33 + l];
    float* op = out + m * NEL;
    #pragma unroll
    for (int i = 0; i < 32; i++) {
        float a = 0.f;
        #pragma unroll
        for (int l = 0; l < 32; l++) a += sX[i * 33 + l] * arow[l];
        op[i * 32 + lane] = a;
    }
}

// ---------------- launch ----------------
extern "C" void kernel_launch(void* const* d_in, const int* in_sizes, int n_in,
                              void* d_out, int out_size) {
    (void)in_sizes; (void)n_in; (void)out_size;
    const float* X = (const float*)d_in[0];
    const float* W = (const float*)d_in[1];
    float* out = (float*)d_out;

    const int LM_SMEM = (1056 + LM_WPB * 2160) * 4;   // 73,344 B
    const int AP_SMEM = (1056 + LM_WPB * 1056) * 4;   // 38,016 B
    cudaFuncSetAttribute(k_logmean, cudaFuncAttributeMaxDynamicSharedMemorySize, LM_SMEM);
    cudaFuncSetAttribute(k_apply,   cudaFuncAttributeMaxDynamicSharedMemorySize, AP_SMEM);

    k_sumA<<<256, 256>>>(X);
    k_redA<<<1, 1024>>>();
    k_prep<<<1, 64>>>(W);
    k_logmean<<<LM_BLOCKS, 256, LM_SMEM>>>(X);
    k_redT1<<<64, 1024>>>();
    k_redT2<<<1, 1024>>>();
    k_final<<<1, 32>>>();
    k_apply<<<LM_BLOCKS, 256, AP_SMEM>>>(X, out);
}

// round 9
// speedup vs baseline: 1.6065x; 1.6065x over previous
#include <cuda_runtime.h>
#include <cuda_bf16.h>
#include <math.h>

// Problem shape (fixed by dataset): X [2048,16,32,32] f32, weight [32,32] f32.
#define NM      32768          // 2048*16 matrices
#define NEL     1024           // 32*32
#define LM_WPB  8              // warps (matrices) per block in heavy kernels
#define LM_BLOCKS (NM / LM_WPB)  // 4096

// ---------------- device scratch (static, no allocation) ----------------
__device__ float d_partA[256 * NEL];        // stage-A block partials
__device__ float d_g0[NEL];                 // arithmetic mean of X
__device__ float d_gs[NEL];                 // sqrtm(g0)
__device__ float d_gis[NEL];                // invsqrtm(g0)
__device__ float d_ws[NEL];                 // sqrtm(weight)
__device__ float d_partT[LM_BLOCKS * NEL];  // per-block logm partial sums (16 MB)
__device__ float d_partT2[64 * NEL];        // second-level partials
__device__ float d_t[NEL];                  // mean of logms
__device__ float d_Af[NEL];                 // final congruence factor ws*gis2

// ---------------- small helpers ----------------
__device__ __forceinline__ void get_pq(int r, int k, int& p, int& q) {
    if (k == 0) { p = 31; q = r; }
    else {
        p = r + k; if (p >= 31) p -= 31;
        q = r - k; if (q < 0)  q += 31;
    }
}

// Warp-cooperative cyclic Jacobi eigensolver for a 32x32 symmetric matrix.
// sA: 32x32 matrix, row-major padded stride 33 (1056 floats). On exit the
// diagonal holds eigenvalues. sV (same layout) holds eigenvectors in columns:
// A_in = V diag(lambda) V^T.  sCS: >= 32 floats scratch.
__device__ void warp_eigh32(float* sA, float* sV, float* sCS, int lane) {
    #pragma unroll
    for (int i = 0; i < 32; i++) sV[i * 33 + lane] = (i == lane) ? 1.0f : 0.0f;
    __syncwarp();

    #pragma unroll 1
    for (int sweep = 0; sweep < 10; sweep++) {
        float off = 0.0f;
        #pragma unroll 1
        for (int r = 0; r < 31; r++) {
            // phase 1: 16 lanes compute the 16 disjoint rotations of this round
            if (lane < 16) {
                int p, q; get_pq(r, lane, p, q);
                float app = sA[p * 33 + p];
                float aqq = sA[q * 33 + q];
                float apq = sA[p * 33 + q];
                off += apq * apq;
                float c = 1.0f, s = 0.0f;
                if (fabsf(apq) > 1e-9f * (fabsf(app) + fabsf(aqq) + 1e-30f)) {
                    float theta = 0.5f * (aqq - app) / apq;
                    float tt = 1.0f / (fabsf(theta) + sqrtf(1.0f + theta * theta));
                    tt = copysignf(tt, theta);
                    c = rsqrtf(1.0f + tt * tt);
                    s = tt * c;
                }
                sCS[lane]      = c;
                sCS[16 + lane] = s;
            }
            __syncwarp();
            // phase 2: column rotations of A and V (lane = row index; conflict-free)
            #pragma unroll
            for (int k = 0; k < 16; k++) {
                float s = sCS[16 + k];
                if (s != 0.0f) {                 // warp-uniform branch
                    float c = sCS[k];
                    int p, q; get_pq(r, k, p, q);
                    float x = sA[lane * 33 + p], y = sA[lane * 33 + q];
                    sA[lane * 33 + p] = c * x - s * y;
                    sA[lane * 33 + q] = s * x + c * y;
                    float vx = sV[lane * 33 + p], vy = sV[lane * 33 + q];
                    sV[lane * 33 + p] = c * vx - s * vy;
                    sV[lane * 33 + q] = s * vx + c * vy;
                }
            }
            __syncwarp();
            // phase 3: row rotations of A (lane = column index; conflict-free)
            #pragma unroll
            for (int k = 0; k < 16; k++) {
                float s = sCS[16 + k];
                if (s != 0.0f) {
                    float c = sCS[k];
                    int p, q; get_pq(r, k, p, q);
                    float x = sA[p * 33 + lane], y = sA[q * 33 + lane];
                    sA[p * 33 + lane] = c * x - s * y;
                    sA[q * 33 + lane] = s * x + c * y;
                }
            }
            __syncwarp();
        }
        // convergence: off-diagonal Frobenius^2 vs diagonal Frobenius^2
        float dd  = sA[lane * 33 + lane];
        float dsq = dd * dd;
        #pragma unroll
        for (int o = 16; o > 0; o >>= 1) {
            off += __shfl_xor_sync(0xffffffffu, off, o);
            dsq += __shfl_xor_sync(0xffffffffu, dsq, o);
        }
        if (off <= 1e-10f * dsq) break;
    }
    __syncwarp();
}

struct FnLog   { __device__ float operator()(float x) const { return logf(fmaxf(x, 1e-30f)); } };
struct FnExp   { __device__ float operator()(float x) const { return expf(x); } };
struct FnSqrt  { __device__ float operator()(float x) const { return sqrtf(fmaxf(x, 0.0f)); } };
struct FnRsqrt { __device__ float operator()(float x) const { return rsqrtf(fmaxf(x, 1e-30f)); } };

// out[i][j] = sum_k V[i][k] f(lambda_k) V[j][k].
// Low-register form: one 32-reg column array + scalar accumulator.
// out may alias sA (diag is consumed into sTmp first); out must NOT alias sV.
template <class F>
__device__ void warp_matfn(const float* sA, const float* sV, float* sTmp,
                           float* out, int ostride, int lane, F f) {
    sTmp[lane] = f(sA[lane * 33 + lane]);
    __syncwarp();
    float vj[32];                     // vj[k] = V[lane][k] * f(lambda_k)
    #pragma unroll
    for (int k = 0; k < 32; k++) vj[k] = sV[lane * 33 + k] * sTmp[k];
    __syncwarp();
    #pragma unroll
    for (int i = 0; i < 32; i++) {
        float acc = 0.0f;
        #pragma unroll
        for (int k = 0; k < 32; k++) acc += sV[i * 33 + k] * vj[k];
        out[i * ostride + lane] = acc;
    }
    __syncwarp();
}

// C = A * B (all 32x32, pad-33 smem). C must not alias A or B.
__device__ void warp_mm(float* C, const float* A, const float* B, int lane) {
    float bcol[32];
    #pragma unroll
    for (int l = 0; l < 32; l++) bcol[l] = B[l * 33 + lane];
    #pragma unroll
    for (int i = 0; i < 32; i++) {
        float acc = 0.0f;
        #pragma unroll
        for (int l = 0; l < 32; l++) acc += A[i * 33 + l] * bcol[l];
        C[i * 33 + lane] = acc;
    }
    __syncwarp();
}

// ---------------- stage A: arithmetic mean of all matrices ----------------
__global__ void k_sumA(const float* __restrict__ X) {
    int b = blockIdx.x, t = threadIdx.x;
    const int MPB = NM / 256;   // 128 matrices per block
    const float* base = X + (size_t)b * MPB * NEL;
    float a0 = 0.f, a1 = 0.f, a2 = 0.f, a3 = 0.f;
    for (int m = 0; m < MPB; m++) {
        const float* p = base + (size_t)m * NEL;
        a0 += p[t];        a1 += p[t + 256];
        a2 += p[t + 512];  a3 += p[t + 768];
    }
    d_partA[b * NEL + t]       = a0;
    d_partA[b * NEL + t + 256] = a1;
    d_partA[b * NEL + t + 512] = a2;
    d_partA[b * NEL + t + 768] = a3;
}

__global__ void k_redA() {
    int e = threadIdx.x;
    float s = 0.f;
    for (int b = 0; b < 256; b++) s += d_partA[b * NEL + e];
    d_g0[e] = s * (1.0f / (float)NM);
}

// ---------------- stage B: gs/gis from g0; ws from weight ----------------
__global__ void k_prep(const float* __restrict__ W) {
    __shared__ float sm[2 * 2160];
    int w = threadIdx.x >> 5, lane = threadIdx.x & 31;
    float* sA  = sm + w * 2160;
    float* sV  = sA + 1056;
    float* sCS = sV + 1056;
    const float* src = (w == 0) ? d_g0 : W;
    #pragma unroll
    for (int i = 0; i < 32; i++) sA[i * 33 + lane] = src[i * 32 + lane];
    __syncwarp();
    warp_eigh32(sA, sV, sCS, lane);
    if (w == 0) {
        warp_matfn(sA, sV, sCS, d_gs,  32, lane, FnSqrt());
        warp_matfn(sA, sV, sCS, d_gis, 32, lane, FnRsqrt());
    } else {
        warp_matfn(sA, sV, sCS, d_ws,  32, lane, FnSqrt());
    }
}

// ---------------- stage C: per-matrix logm(sym(gis X gis)), block-summed --
__global__ __launch_bounds__(256, 2) void k_logmean(const float* __restrict__ X) {
    extern __shared__ float sm[];
    float* gis_s = sm;                                  // 1056
    int tid = threadIdx.x, w = tid >> 5, lane = tid & 31;
    for (int e = tid; e < NEL; e += 256)
        gis_s[(e >> 5) * 33 + (e & 31)] = d_gis[e];
    __syncthreads();

    float* sA  = sm + 1056 + w * 2160;
    float* sV  = sA + 1056;
    float* sCS = sV + 1056;                             // 48 floats

    size_t m = (size_t)blockIdx.x * LM_WPB + w;
    const float* xp = X + m * NEL;
    #pragma unroll
    for (int i = 0; i < 32; i++) sA[i * 33 + lane] = xp[i * 32 + lane];
    __syncwarp();

    // Low-register congruence: U = X*gis into sV, then M = gis*U into sA.
    {
        float col[32];
        #pragma unroll
        for (int l = 0; l < 32; l++) col[l] = gis_s[l * 33 + lane];  // gis[:,lane]
        #pragma unroll
        for (int i = 0; i < 32; i++) {
            float acc = 0.f;
            #pragma unroll
            for (int l = 0; l < 32; l++) acc += sA[i * 33 + l] * col[l];
            sV[i * 33 + lane] = acc;                                  // U[i][lane]
        }
        __syncwarp();
        #pragma unroll
        for (int l = 0; l < 32; l++) col[l] = sV[l * 33 + lane];      // U[:,lane]
        __syncwarp();
        #pragma unroll
        for (int i = 0; i < 32; i++) {
            float acc = 0.f;
            #pragma unroll
            for (int l = 0; l < 32; l++) acc += gis_s[i * 33 + l] * col[l];
            sA[i * 33 + lane] = acc;                                  // M[i][lane]
        }
        __syncwarp();
    }
    // symmetrize (matches reference _sym)
    for (int i = 0; i < lane; i++) {
        float a = sA[i * 33 + lane], b = sA[lane * 33 + i];
        float h = 0.5f * (a + b);
        sA[i * 33 + lane] = h; sA[lane * 33 + i] = h;
    }
    __syncwarp();

    warp_eigh32(sA, sV, sCS, lane);
    warp_matfn(sA, sV, sCS, sA, 33, lane, FnLog());   // sA = logm(M)

    __syncthreads();
    // deterministic fixed-order block reduction over the 8 warp buffers
    float* outp = d_partT + (size_t)blockIdx.x * NEL;
    for (int e = tid; e < NEL; e += 256) {
        int i = e >> 5, j = e & 31;
        float s = 0.f;
        #pragma unroll
        for (int ww = 0; ww < LM_WPB; ww++)
            s += sm[1056 + ww * 2160 + i * 33 + j];
        outp[e] = s;
    }
}

__global__ void k_redT1() {
    int b = blockIdx.x, e = threadIdx.x;
    float s = 0.f;
    for (int i = 0; i < LM_BLOCKS / 64; i++)
        s += d_partT[((size_t)(b * (LM_BLOCKS / 64) + i)) * NEL + e];
    d_partT2[b * NEL + e] = s;
}

__global__ void k_redT2() {
    int e = threadIdx.x;
    float s = 0.f;
    for (int b = 0; b < 64; b++) s += d_partT2[b * NEL + e];
    d_t[e] = s * (1.0f / (float)NM);
}

// ---------------- stage D: Karcher update + final factor A_f --------------
__global__ void k_final() {
    __shared__ float sm[4 * 1056 + 48];
    float* sA  = sm;
    float* sV  = sm + 1056;
    float* sB  = sm + 2112;
    float* sC  = sm + 3168;
    float* sCS = sm + 4224;
    int lane = threadIdx.x;

    // E = expm(t)
    #pragma unroll
    for (int i = 0; i < 32; i++) sA[i * 33 + lane] = d_t[i * 32 + lane];
    __syncwarp();
    warp_eigh32(sA, sV, sCS, lane);
    warp_matfn(sA, sV, sCS, sB, 33, lane, FnExp());   // sB = E

    // g = sym(gs * E * gs)
    #pragma unroll
    for (int i = 0; i < 32; i++) sC[i * 33 + lane] = d_gs[i * 32 + lane];
    __syncwarp();
    warp_mm(sA, sC, sB, lane);                        // sA = gs*E
    warp_mm(sV, sA, sC, lane);                        // sV = gs*E*gs
    for (int i = 0; i < lane; i++) {
        float a = sV[i * 33 + lane], b = sV[lane * 33 + i];
        float h = 0.5f * (a + b);
        sV[i * 33 + lane] = h; sV[lane * 33 + i] = h;
    }
    __syncwarp();

    // gis2 = invsqrtm(g)
    warp_eigh32(sV, sB, sCS, lane);                   // matrix in sV, vectors in sB
    warp_matfn(sV, sB, sCS, sA, 33, lane, FnRsqrt()); // sA = gis2

    // A_f = ws * gis2
    #pragma unroll
    for (int i = 0; i < 32; i++) sC[i * 33 + lane] = d_ws[i * 32 + lane];
    __syncwarp();
    warp_mm(sB, sC, sA, lane);                        // sB = ws*gis2
    #pragma unroll
    for (int i = 0; i < 32; i++) d_Af[i * 32 + lane] = sB[i * 33 + lane];
}

// ---------------- stage E: out = A_f * X * A_f^T per matrix ---------------
__global__ __launch_bounds__(256, 2) void k_apply(const float* __restrict__ X,
                                                  float* __restrict__ out) {
    extern __shared__ float sm[];
    float* A_s = sm;                                   // 1056, block-shared
    int tid = threadIdx.x, w = tid >> 5, lane = tid & 31;
    for (int e = tid; e < NEL; e += 256)
        A_s[(e >> 5) * 33 + (e & 31)] = d_Af[e];
    __syncthreads();

    float* sX = sm + 1056 + w * 1056;                  // per-warp T buffer
    size_t m = (size_t)blockIdx.x * LM_WPB + w;
    const float* xp = X + m * NEL;

    float col[32];
    #pragma unroll
    for (int i = 0; i < 32; i++) col[i] = xp[i * 32 + lane];   // X[:,lane]

    // T = A * X  (write straight to smem; scalar accumulator)
    #pragma unroll
    for (int i = 0; i < 32; i++) {
        float acc = 0.f;
        #pragma unroll
        for (int l = 0; l < 32; l++) acc += A_s[i * 33 + l] * col[l];
        sX[i * 33 + lane] = acc;
    }
    __syncwarp();

    // Y = T * A^T :  Y[i][lane] = sum_l T[i][l] * A[lane][l]
    #pragma unroll
    for (int l = 0; l < 32; l++) col[l] = A_s[lane * 33 + l];
    float* op = out + m * NEL;
    #pragma unroll
    for (int i = 0; i < 32; i++) {
        float acc = 0.f;
        #pragma unroll
        for (int l = 0; l < 32; l++) acc += sX[i * 33 + l] * col[l];
        op[i * 32 + lane] = acc;
    }
}

// ---------------- launch ----------------
extern "C" void kernel_launch(void* const* d_in, const int* in_sizes, int n_in,
                              void* d_out, int out_size) {
    (void)in_sizes; (void)n_in; (void)out_size;
    const float* X = (const float*)d_in[0];
    const float* W = (const float*)d_in[1];
    float* out = (float*)d_out;

    const int LM_SMEM = (1056 + LM_WPB * 2160) * 4;   // 73,344 B
    const int AP_SMEM = (1056 + LM_WPB * 1056) * 4;   // 38,016 B
    cudaFuncSetAttribute(k_logmean, cudaFuncAttributeMaxDynamicSharedMemorySize, LM_SMEM);
    cudaFuncSetAttribute(k_apply,   cudaFuncAttributeMaxDynamicSharedMemorySize, AP_SMEM);

    k_sumA<<<256, 256>>>(X);
    k_redA<<<1, 1024>>>();
    k_prep<<<1, 64>>>(W);
    k_logmean<<<LM_BLOCKS, 256, LM_SMEM>>>(X);
    k_redT1<<<64, 1024>>>();
    k_redT2<<<1, 1024>>>();
    k_final<<<1, 32>>>();
    k_apply<<<LM_BLOCKS, 256, AP_SMEM>>>(X, out);
}

// round 10
// speedup vs baseline: 2.0913x; 1.3018x over previous
#include <cuda_runtime.h>
#include <cuda_bf16.h>
#include <math.h>

// Problem shape (fixed by dataset): X [2048,16,32,32] f32, weight [32,32] f32.
#define NM      32768          // 2048*16 matrices
#define NEL     1024           // 32*32
#define LM_WPB  8              // warps (matrices) per block in heavy kernels
#define LM_BLOCKS (NM / LM_WPB)  // 4096

// ---------------- device scratch (static, no allocation) ----------------
__device__ float d_partA[256 * NEL];        // stage-A block partials
__device__ float d_g0[NEL];                 // arithmetic mean of X
__device__ float d_gs[NEL];                 // sqrtm(g0)
__device__ float d_gis[NEL];                // invsqrtm(g0)
__device__ float d_ws[NEL];                 // sqrtm(weight)
__device__ float d_partT[LM_BLOCKS * NEL];  // per-block logm partial sums (16 MB)
__device__ float d_partT2[64 * NEL];        // second-level partials
__device__ float d_t[NEL];                  // mean of logms
__device__ float d_Af[NEL];                 // final congruence factor ws*gis2

// ---------------- small helpers ----------------
__device__ __forceinline__ void get_pq(int r, int k, int& p, int& q) {
    if (k == 0) { p = 31; q = r; }
    else {
        p = r + k; if (p >= 31) p -= 31;
        q = r - k; if (q < 0)  q += 31;
    }
}

// Warp-cooperative cyclic Jacobi eigensolver for a 32x32 symmetric matrix.
// sA: 32x32 matrix, row-major padded stride 33 (1056 floats). On exit the
// diagonal holds eigenvalues. sV (same layout) holds eigenvectors in columns:
// A_in = V diag(lambda) V^T.  sCS: >= 32 floats scratch.
// tol:  sweep break when off_F^2 <= tol * diag_F^2
// skip: per-rotation skip when |apq| <= skip * (|app|+|aqq|)
__device__ void warp_eigh32(float* sA, float* sV, float* sCS, int lane,
                            float tol, float skip) {
    #pragma unroll
    for (int i = 0; i < 32; i++) sV[i * 33 + lane] = (i == lane) ? 1.0f : 0.0f;
    __syncwarp();

    #pragma unroll 1
    for (int sweep = 0; sweep < 10; sweep++) {
        float off = 0.0f;
        #pragma unroll 1
        for (int r = 0; r < 31; r++) {
            // phase 1: 16 lanes compute the 16 disjoint rotations of this round
            if (lane < 16) {
                int p, q; get_pq(r, lane, p, q);
                float app = sA[p * 33 + p];
                float aqq = sA[q * 33 + q];
                float apq = sA[p * 33 + q];
                off += apq * apq;
                float c = 1.0f, s = 0.0f;
                if (fabsf(apq) > skip * (fabsf(app) + fabsf(aqq) + 1e-30f)) {
                    float theta = 0.5f * (aqq - app) / apq;
                    float tt = 1.0f / (fabsf(theta) + sqrtf(1.0f + theta * theta));
                    tt = copysignf(tt, theta);
                    c = rsqrtf(1.0f + tt * tt);
                    s = tt * c;
                }
                sCS[lane]      = c;
                sCS[16 + lane] = s;
            }
            __syncwarp();
            // phase 2: column rotations of A and V (lane = row index; conflict-free)
            #pragma unroll
            for (int k = 0; k < 16; k++) {
                float s = sCS[16 + k];
                if (s != 0.0f) {                 // warp-uniform branch
                    float c = sCS[k];
                    int p, q; get_pq(r, k, p, q);
                    float x = sA[lane * 33 + p], y = sA[lane * 33 + q];
                    sA[lane * 33 + p] = c * x - s * y;
                    sA[lane * 33 + q] = s * x + c * y;
                    float vx = sV[lane * 33 + p], vy = sV[lane * 33 + q];
                    sV[lane * 33 + p] = c * vx - s * vy;
                    sV[lane * 33 + q] = s * vx + c * vy;
                }
            }
            __syncwarp();
            // phase 3: row rotations of A (lane = column index; conflict-free)
            #pragma unroll
            for (int k = 0; k < 16; k++) {
                float s = sCS[16 + k];
                if (s != 0.0f) {
                    float c = sCS[k];
                    int p, q; get_pq(r, k, p, q);
                    float x = sA[p * 33 + lane], y = sA[q * 33 + lane];
                    sA[p * 33 + lane] = c * x - s * y;
                    sA[q * 33 + lane] = s * x + c * y;
                }
            }
            __syncwarp();
        }
        // convergence: off-diagonal Frobenius^2 vs diagonal Frobenius^2
        float dd  = sA[lane * 33 + lane];
        float dsq = dd * dd;
        #pragma unroll
        for (int o = 16; o > 0; o >>= 1) {
            off += __shfl_xor_sync(0xffffffffu, off, o);
            dsq += __shfl_xor_sync(0xffffffffu, dsq, o);
        }
        if (off <= tol * dsq) break;
    }
    __syncwarp();
}

struct FnLog   { __device__ float operator()(float x) const { return logf(fmaxf(x, 1e-30f)); } };
struct FnExp   { __device__ float operator()(float x) const { return expf(x); } };
struct FnSqrt  { __device__ float operator()(float x) const { return sqrtf(fmaxf(x, 0.0f)); } };
struct FnRsqrt { __device__ float operator()(float x) const { return rsqrtf(fmaxf(x, 1e-30f)); } };

// out[i][j] = sum_k V[i][k] f(lambda_k) V[j][k].
// Low-register form: one 32-reg column array + scalar accumulator.
// out may alias sA (diag is consumed into sTmp first); out must NOT alias sV.
template <class F>
__device__ void warp_matfn(const float* sA, const float* sV, float* sTmp,
                           float* out, int ostride, int lane, F f) {
    sTmp[lane] = f(sA[lane * 33 + lane]);
    __syncwarp();
    float vj[32];                     // vj[k] = V[lane][k] * f(lambda_k)
    #pragma unroll
    for (int k = 0; k < 32; k++) vj[k] = sV[lane * 33 + k] * sTmp[k];
    __syncwarp();
    #pragma unroll
    for (int i = 0; i < 32; i++) {
        float acc = 0.0f;
        #pragma unroll
        for (int k = 0; k < 32; k++) acc += sV[i * 33 + k] * vj[k];
        out[i * ostride + lane] = acc;
    }
    __syncwarp();
}

// C = A * B (all 32x32, pad-33 smem). C must not alias A or B.
__device__ void warp_mm(float* C, const float* A, const float* B, int lane) {
    float bcol[32];
    #pragma unroll
    for (int l = 0; l < 32; l++) bcol[l] = B[l * 33 + lane];
    #pragma unroll
    for (int i = 0; i < 32; i++) {
        float acc = 0.0f;
        #pragma unroll
        for (int l = 0; l < 32; l++) acc += A[i * 33 + l] * bcol[l];
        C[i * 33 + lane] = acc;
    }
    __syncwarp();
}

// ---------------- stage A: arithmetic mean of all matrices ----------------
__global__ void k_sumA(const float* __restrict__ X) {
    int b = blockIdx.x, t = threadIdx.x;
    const int MPB = NM / 256;   // 128 matrices per block
    const float* base = X + (size_t)b * MPB * NEL;
    float a0 = 0.f, a1 = 0.f, a2 = 0.f, a3 = 0.f;
    for (int m = 0; m < MPB; m++) {
        const float* p = base + (size_t)m * NEL;
        a0 += p[t];        a1 += p[t + 256];
        a2 += p[t + 512];  a3 += p[t + 768];
    }
    d_partA[b * NEL + t]       = a0;
    d_partA[b * NEL + t + 256] = a1;
    d_partA[b * NEL + t + 512] = a2;
    d_partA[b * NEL + t + 768] = a3;
}

__global__ void k_redA() {
    int e = blockIdx.x * 256 + threadIdx.x;
    float s = 0.f;
    #pragma unroll 8
    for (int b = 0; b < 256; b++) s += d_partA[b * NEL + e];
    d_g0[e] = s * (1.0f / (float)NM);
}

// ---------------- stage B: gs/gis from g0; ws from weight ----------------
__global__ void k_prep(const float* __restrict__ W) {
    __shared__ float sm[2 * 2160];
    int w = threadIdx.x >> 5, lane = threadIdx.x & 31;
    float* sA  = sm + w * 2160;
    float* sV  = sA + 1056;
    float* sCS = sV + 1056;
    const float* src = (w == 0) ? d_g0 : W;
    #pragma unroll
    for (int i = 0; i < 32; i++) sA[i * 33 + lane] = src[i * 32 + lane];
    __syncwarp();
    warp_eigh32(sA, sV, sCS, lane, 1e-10f, 1e-9f);
    if (w == 0) {
        warp_matfn(sA, sV, sCS, d_gs,  32, lane, FnSqrt());
        warp_matfn(sA, sV, sCS, d_gis, 32, lane, FnRsqrt());
    } else {
        warp_matfn(sA, sV, sCS, d_ws,  32, lane, FnSqrt());
    }
}

// ---------------- stage C: per-matrix logm(sym(gis X gis)), block-summed --
__global__ __launch_bounds__(256, 3) void k_logmean(const float* __restrict__ X) {
    extern __shared__ float sm[];
    float* gis_s = sm;                                  // 1056
    int tid = threadIdx.x, w = tid >> 5, lane = tid & 31;
    for (int e = tid; e < NEL; e += 256)
        gis_s[(e >> 5) * 33 + (e & 31)] = d_gis[e];
    __syncthreads();

    float* sA  = sm + 1056 + w * 2160;
    float* sV  = sA + 1056;
    float* sCS = sV + 1056;                             // 48 floats

    size_t m = (size_t)blockIdx.x * LM_WPB + w;
    const float* xp = X + m * NEL;
    #pragma unroll
    for (int i = 0; i < 32; i++) sA[i * 33 + lane] = xp[i * 32 + lane];
    __syncwarp();

    // Low-register congruence: U = X*gis into sV, then M = gis*U into sA.
    {
        float col[32];
        #pragma unroll
        for (int l = 0; l < 32; l++) col[l] = gis_s[l * 33 + lane];  // gis[:,lane]
        #pragma unroll
        for (int i = 0; i < 32; i++) {
            float acc = 0.f;
            #pragma unroll
            for (int l = 0; l < 32; l++) acc += sA[i * 33 + l] * col[l];
            sV[i * 33 + lane] = acc;                                  // U[i][lane]
        }
        __syncwarp();
        #pragma unroll
        for (int l = 0; l < 32; l++) col[l] = sV[l * 33 + lane];      // U[:,lane]
        __syncwarp();
        #pragma unroll
        for (int i = 0; i < 32; i++) {
            float acc = 0.f;
            #pragma unroll
            for (int l = 0; l < 32; l++) acc += gis_s[i * 33 + l] * col[l];
            sA[i * 33 + lane] = acc;                                  // M[i][lane]
        }
        __syncwarp();
    }
    // symmetrize (matches reference _sym)
    for (int i = 0; i < lane; i++) {
        float a = sA[i * 33 + lane], b = sA[lane * 33 + i];
        float h = 0.5f * (a + b);
        sA[i * 33 + lane] = h; sA[lane * 33 + i] = h;
    }
    __syncwarp();

    // Relaxed tolerance: per-matrix logm error averages down ~sqrt(32768)x
    // in the batch mean, so 1e-8 (break) / 1e-7 (skip) is plenty.
    warp_eigh32(sA, sV, sCS, lane, 1e-8f, 1e-7f);
    warp_matfn(sA, sV, sCS, sA, 33, lane, FnLog());   // sA = logm(M)

    __syncthreads();
    // deterministic fixed-order block reduction over the 8 warp buffers
    float* outp = d_partT + (size_t)blockIdx.x * NEL;
    for (int e = tid; e < NEL; e += 256) {
        int i = e >> 5, j = e & 31;
        float s = 0.f;
        #pragma unroll
        for (int ww = 0; ww < LM_WPB; ww++)
            s += sm[1056 + ww * 2160 + i * 33 + j];
        outp[e] = s;
    }
}

__global__ void k_redT1() {
    int b = blockIdx.x, e = threadIdx.x;
    float s = 0.f;
    for (int i = 0; i < LM_BLOCKS / 64; i++)
        s += d_partT[((size_t)(b * (LM_BLOCKS / 64) + i)) * NEL + e];
    d_partT2[b * NEL + e] = s;
}

__global__ void k_redT2() {
    int e = threadIdx.x;
    float s = 0.f;
    for (int b = 0; b < 64; b++) s += d_partT2[b * NEL + e];
    d_t[e] = s * (1.0f / (float)NM);
}

// ---------------- stage D: Karcher update + final factor A_f --------------
__global__ void k_final() {
    __shared__ float sm[4 * 1056 + 48];
    float* sA  = sm;
    float* sV  = sm + 1056;
    float* sB  = sm + 2112;
    float* sC  = sm + 3168;
    float* sCS = sm + 4224;
    int lane = threadIdx.x;

    // E = expm(t)
    #pragma unroll
    for (int i = 0; i < 32; i++) sA[i * 33 + lane] = d_t[i * 32 + lane];
    __syncwarp();
    warp_eigh32(sA, sV, sCS, lane, 1e-10f, 1e-9f);
    warp_matfn(sA, sV, sCS, sB, 33, lane, FnExp());   // sB = E

    // g = sym(gs * E * gs)
    #pragma unroll
    for (int i = 0; i < 32; i++) sC[i * 33 + lane] = d_gs[i * 32 + lane];
    __syncwarp();
    warp_mm(sA, sC, sB, lane);                        // sA = gs*E
    warp_mm(sV, sA, sC, lane);                        // sV = gs*E*gs
    for (int i = 0; i < lane; i++) {
        float a = sV[i * 33 + lane], b = sV[lane * 33 + i];
        float h = 0.5f * (a + b);
        sV[i * 33 + lane] = h; sV[lane * 33 + i] = h;
    }
    __syncwarp();

    // gis2 = invsqrtm(g)
    warp_eigh32(sV, sB, sCS, lane, 1e-10f, 1e-9f);    // matrix in sV, vectors in sB
    warp_matfn(sV, sB, sCS, sA, 33, lane, FnRsqrt()); // sA = gis2

    // A_f = ws * gis2
    #pragma unroll
    for (int i = 0; i < 32; i++) sC[i * 33 + lane] = d_ws[i * 32 + lane];
    __syncwarp();
    warp_mm(sB, sC, sA, lane);                        // sB = ws*gis2
    #pragma unroll
    for (int i = 0; i < 32; i++) d_Af[i * 32 + lane] = sB[i * 33 + lane];
}

// ---------------- stage E: out = A_f * X * A_f^T per matrix ---------------
__global__ __launch_bounds__(256, 3) void k_apply(const float* __restrict__ X,
                                                  float* __restrict__ out) {
    extern __shared__ float sm[];
    float* A_s = sm;                                   // 1056, block-shared
    int tid = threadIdx.x, w = tid >> 5, lane = tid & 31;
    for (int e = tid; e < NEL; e += 256)
        A_s[(e >> 5) * 33 + (e & 31)] = d_Af[e];
    __syncthreads();

    float* sX = sm + 1056 + w * 1056;                  // per-warp T buffer
    size_t m = (size_t)blockIdx.x * LM_WPB + w;
    const float* xp = X + m * NEL;

    float col[32];
    #pragma unroll
    for (int i = 0; i < 32; i++) col[i] = xp[i * 32 + lane];   // X[:,lane]

    // T = A * X  (write straight to smem; scalar accumulator)
    #pragma unroll
    for (int i = 0; i < 32; i++) {
        float acc = 0.f;
        #pragma unroll
        for (int l = 0; l < 32; l++) acc += A_s[i * 33 + l] * col[l];
        sX[i * 33 + lane] = acc;
    }
    __syncwarp();

    // Y = T * A^T :  Y[i][lane] = sum_l T[i][l] * A[lane][l]
    #pragma unroll
    for (int l = 0; l < 32; l++) col[l] = A_s[lane * 33 + l];
    float* op = out + m * NEL;
    #pragma unroll
    for (int i = 0; i < 32; i++) {
        float acc = 0.f;
        #pragma unroll
        for (int l = 0; l < 32; l++) acc += sX[i * 33 + l] * col[l];
        op[i * 32 + lane] = acc;
    }
}

// ---------------- launch ----------------
extern "C" void kernel_launch(void* const* d_in, const int* in_sizes, int n_in,
                              void* d_out, int out_size) {
    (void)in_sizes; (void)n_in; (void)out_size;
    const float* X = (const float*)d_in[0];
    const float* W = (const float*)d_in[1];
    float* out = (float*)d_out;

    const int LM_SMEM = (1056 + LM_WPB * 2160) * 4;   // 73,344 B
    const int AP_SMEM = (1056 + LM_WPB * 1056) * 4;   // 38,016 B
    cudaFuncSetAttribute(k_logmean, cudaFuncAttributeMaxDynamicSharedMemorySize, LM_SMEM);
    cudaFuncSetAttribute(k_apply,   cudaFuncAttributeMaxDynamicSharedMemorySize, AP_SMEM);

    k_sumA<<<256, 256>>>(X);
    k_redA<<<4, 256>>>();
    k_prep<<<1, 64>>>(W);
    k_logmean<<<LM_BLOCKS, 256, LM_SMEM>>>(X);
    k_redT1<<<64, 1024>>>();
    k_redT2<<<1, 1024>>>();
    k_final<<<1, 32>>>();
    k_apply<<<LM_BLOCKS, 256, AP_SMEM>>>(X, out);
}